// round 13
// baseline (speedup 1.0000x reference)
#include <cuda_runtime.h>
#include <math_constants.h>
#include <cstdint>

// Problem shape (fixed by the dataset): B=64, N=4096, D2=128, S=512
#define D2 128
#define MAXB 64
#define MAXN 4096
#define SLICES 16       // blocks per batch
#define SMAX 512
#define DEPTH 4         // pipeline stages
#define STAGE_ROWS 32
#define STAGE_BYTES (STAGE_ROWS * D2 * 4)   // 16 KB

// Scratch (no cudaMalloc allowed)
__device__ float g_logits[MAXB * MAXN];       // 1 MB
__device__ unsigned g_done[MAXB];             // zero-init; returns to 0 each run

__device__ __forceinline__ uint32_t smem_u32(const void* p) {
    uint32_t a;
    asm("{ .reg .u64 t; cvta.to.shared.u64 t, %1; cvt.u32.u64 %0, t; }"
        : "=r"(a) : "l"(p));
    return a;
}

__device__ __forceinline__ void mbar_init(uint32_t addr, uint32_t count) {
    asm volatile("mbarrier.init.shared.b64 [%0], %1;" :: "r"(addr), "r"(count) : "memory");
}
__device__ __forceinline__ void mbar_expect_tx(uint32_t addr, uint32_t bytes) {
    asm volatile("mbarrier.arrive.expect_tx.shared.b64 _, [%0], %1;"
                 :: "r"(addr), "r"(bytes) : "memory");
}
__device__ __forceinline__ void mbar_wait(uint32_t addr, uint32_t parity) {
    asm volatile(
        "{\n\t"
        ".reg .pred P1;\n\t"
        "WAIT_LOOP_%=:\n\t"
        "mbarrier.try_wait.parity.acquire.cta.shared::cta.b64 P1, [%0], %1, 0x989680;\n\t"
        "@P1 bra.uni WAIT_DONE_%=;\n\t"
        "bra.uni WAIT_LOOP_%=;\n\t"
        "WAIT_DONE_%=:\n\t"
        "}"
        :: "r"(addr), "r"(parity) : "memory");
}

// Bulk async copy global -> shared::cta with L2 eviction-policy hint.
__device__ __forceinline__ void bulk_copy(uint32_t dst, const void* src,
                                          uint32_t bytes, uint32_t mbar, bool keep) {
    if (keep) {
        asm volatile(
            "{\n\t.reg .b64 pol;\n\t"
            "createpolicy.fractional.L2::evict_last.b64 pol, 1.0;\n\t"
            "cp.async.bulk.shared::cta.global.mbarrier::complete_tx::bytes.L2::cache_hint"
            " [%0], [%1], %2, [%3], pol;\n\t}"
            :: "r"(dst), "l"(src), "r"(bytes), "r"(mbar) : "memory");
    } else {
        asm volatile(
            "{\n\t.reg .b64 pol;\n\t"
            "createpolicy.fractional.L2::evict_first.b64 pol, 1.0;\n\t"
            "cp.async.bulk.shared::cta.global.mbarrier::complete_tx::bytes.L2::cache_hint"
            " [%0], [%1], %2, [%3], pol;\n\t}"
            :: "r"(dst), "l"(src), "r"(bytes), "r"(mbar) : "memory");
    }
}

// ---------------------------------------------------------------------------
// Fused kernel with bulk-async (TMA-path) streaming pipeline:
//   producer (1 elected thread) enqueues 16 KB stage copies of y_past into a
//   4-deep smem ring; consumers compute logits from smem via LDS.128.
//   L2 residency split kept via createpolicy hints (evict_last / evict_first).
//   Epilogue: last block per batch does softmax + scatter-add + normalize.
// grid = (SLICES, B), block = 256
// ---------------------------------------------------------------------------
__global__ __launch_bounds__(256) void fused_kernel(const int* __restrict__ s_past,
                                                    const float* __restrict__ yq,
                                                    const float* __restrict__ y_past,
                                                    const float* __restrict__ w,
                                                    float* __restrict__ out,
                                                    int N, int S, int resident_rows) {
    extern __shared__ char smem_dyn[];                 // DEPTH * STAGE_BYTES
    __shared__ unsigned long long mbar_full[DEPTH];
    __shared__ float  syq[D2];
    __shared__ float4 part4[8][D2 / 4];                // 4 KB
    __shared__ float  sq[D2];
    __shared__ float  bins[SMAX];                      // epilogue only
    __shared__ float  red[8];
    __shared__ float  bcast;
    __shared__ unsigned sflag;

    const int b = blockIdx.y;
    const int t = threadIdx.x;                         // 0..255

    const int rows_per_block = N / SLICES;             // 256
    const int block_row0 = blockIdx.x * rows_per_block;
    const int n_iters = rows_per_block / STAGE_ROWS;   // 8
    const bool keep = (block_row0 + rows_per_block) <= resident_rows;

    const float* __restrict__ ybase = y_past + (size_t)b * N * D2;
    const uint32_t stage0 = smem_u32(smem_dyn);
    const uint32_t mbar0  = smem_u32(mbar_full);

    // ---------- init barriers and launch the first DEPTH copies ----------
    if (t == 0) {
#pragma unroll
        for (int s = 0; s < DEPTH; s++) mbar_init(mbar0 + 8 * s, 1);
    }
    __syncthreads();
    if (t == 0) {
#pragma unroll
        for (int s = 0; s < DEPTH; s++) {
            mbar_expect_tx(mbar0 + 8 * s, STAGE_BYTES);
            bulk_copy(stage0 + s * STAGE_BYTES,
                      ybase + (size_t)(block_row0 + s * STAGE_ROWS) * D2,
                      STAGE_BYTES, mbar0 + 8 * s, keep);
        }
    }

    // ---------- prologue: q = yq @ W (overlaps the first TMA copies) ----------
    if (t < D2) syq[t] = yq[b * D2 + t];
    __syncthreads();
    {
        const int dg = t & 31;              // float4 column group (4 d's)
        const int h  = t >> 5;              // 0..7: e-chunk of 16
        const float4* __restrict__ w4 = reinterpret_cast<const float4*>(w);
        float4 acc = make_float4(0.f, 0.f, 0.f, 0.f);
#pragma unroll
        for (int j = 0; j < 16; j++) {
            const int e = h * 16 + j;
            const float4 wv = w4[e * 32 + dg];
            const float s = syq[e];
            acc.x = fmaf(s, wv.x, acc.x);
            acc.y = fmaf(s, wv.y, acc.y);
            acc.z = fmaf(s, wv.z, acc.z);
            acc.w = fmaf(s, wv.w, acc.w);
        }
        part4[h][dg] = acc;
    }
    __syncthreads();
    if (t < D2) {
        const float* p = reinterpret_cast<const float*>(part4);
        float s = 0.f;
#pragma unroll
        for (int h = 0; h < 8; h++) s += p[h * D2 + t];
        sq[t] = s;
    }
    __syncthreads();

    // ---------- body: consume stages ----------
    const int warp = t >> 5;                // 0..7
    const int lane = t & 31;
    const int g = lane >> 3;                // 0..3 (row within warp's 4)
    const int c = lane & 7;                 // 0..7 (float4 chunk)

    const float4* sq4 = reinterpret_cast<const float4*>(sq);
    const float4 q0 = sq4[c];
    const float4 q1 = sq4[c + 8];
    const float4 q2 = sq4[c + 16];
    const float4 q3 = sq4[c + 24];

    const int rl = warp * 4 + g;            // row within stage (0..31)

    for (int it = 0; it < n_iters; it++) {
        const int s = it & (DEPTH - 1);
        mbar_wait(mbar0 + 8 * s, (it / DEPTH) & 1);

        const float4* row = reinterpret_cast<const float4*>(
            smem_dyn + s * STAGE_BYTES) + rl * 32;
        float4 v0 = row[c];
        float4 v1 = row[c + 8];
        float4 v2 = row[c + 16];
        float4 v3 = row[c + 24];

        float a;
        a = fmaf(v0.x, q0.x, fmaf(v0.y, q0.y, fmaf(v0.z, q0.z, v0.w * q0.w)));
        a = fmaf(v1.x, q1.x, fmaf(v1.y, q1.y, fmaf(v1.z, q1.z, fmaf(v1.w, q1.w, a))));
        a = fmaf(v2.x, q2.x, fmaf(v2.y, q2.y, fmaf(v2.z, q2.z, fmaf(v2.w, q2.w, a))));
        a = fmaf(v3.x, q3.x, fmaf(v3.y, q3.y, fmaf(v3.z, q3.z, fmaf(v3.w, q3.w, a))));

#pragma unroll
        for (int o = 1; o <= 4; o <<= 1) a += __shfl_xor_sync(0xffffffffu, a, o);

        if (c == 0) {
            g_logits[(size_t)b * N + block_row0 + it * STAGE_ROWS + rl] = a;
        }

        __syncthreads();     // all lanes done reading stage s
        const int nxt = it + DEPTH;
        if (t == 0 && nxt < n_iters) {
            mbar_expect_tx(mbar0 + 8 * s, STAGE_BYTES);
            bulk_copy(stage0 + s * STAGE_BYTES,
                      ybase + (size_t)(block_row0 + nxt * STAGE_ROWS) * D2,
                      STAGE_BYTES, mbar0 + 8 * s, keep);
        }
    }

    // ---------- epilogue: last block for batch b does softmax + scatter ----------
    __threadfence();
    __syncthreads();
    if (t == 0) sflag = atomicAdd(&g_done[b], 1u);
    __syncthreads();
    if (sflag != SLICES - 1) return;

    for (int s = t; s < S; s += 256) bins[s] = 0.f;

    float vals[16];
    int   sid[16];
    float mx = -CUDART_INF_F;
#pragma unroll
    for (int i = 0; i < 16; i++) {
        vals[i] = __ldcg(&g_logits[(size_t)b * N + t + i * 256]);
        sid[i]  = __ldg(&s_past[(size_t)b * N + t + i * 256]);
    }
#pragma unroll
    for (int i = 0; i < 16; i++) mx = fmaxf(mx, vals[i]);

#pragma unroll
    for (int o = 16; o; o >>= 1) mx = fmaxf(mx, __shfl_xor_sync(0xffffffffu, mx, o));
    if (lane == 0) red[warp] = mx;
    __syncthreads();
    if (t < 8) {
        float m = red[t];
#pragma unroll
        for (int o = 4; o; o >>= 1) m = fmaxf(m, __shfl_xor_sync(0xffu, m, o));
        if (t == 0) bcast = m;
    }
    __syncthreads();
    mx = bcast;

    float sum = 0.f;
#pragma unroll
    for (int i = 0; i < 16; i++) {
        float e = __expf(vals[i] - mx);
        sum += e;
        atomicAdd(&bins[sid[i]], e);
    }
    __syncthreads();

#pragma unroll
    for (int o = 16; o; o >>= 1) sum += __shfl_xor_sync(0xffffffffu, sum, o);
    if (lane == 0) red[warp] = sum;
    __syncthreads();
    if (t < 8) {
        float s2 = red[t];
#pragma unroll
        for (int o = 4; o; o >>= 1) s2 += __shfl_xor_sync(0xffu, s2, o);
        if (t == 0) bcast = s2;
    }
    __syncthreads();
    const float inv_z = 1.0f / bcast;

    for (int s = t; s < S; s += 256) {
        out[(size_t)b * S + s] = bins[s] * inv_z;
    }

    // Reset counter for the next graph replay (deterministic across calls)
    if (t == 0) g_done[b] = 0;
}

// ---------------------------------------------------------------------------
// kernel_launch
// Inputs (metadata order): s_past (int32, B*N), yq (f32, B*D2),
//                          y_past (f32, B*N*D2), w_mat (f32, D2*D2),
//                          size_s (int scalar, on device)
// Output: post_est (f32, B*S)
// ---------------------------------------------------------------------------
extern "C" void kernel_launch(void* const* d_in, const int* in_sizes, int n_in,
                              void* d_out, int out_size) {
    const int*   s_past = (const int*)d_in[0];
    const float* yq     = (const float*)d_in[1];
    const float* y_past = (const float*)d_in[2];
    const float* w_mat  = (const float*)d_in[3];
    float*       out    = (float*)d_out;

    const int D = D2;                       // 128
    const int B = in_sizes[1] / D;          // 64
    const int N = in_sizes[0] / B;          // 4096
    const int S = out_size / B;             // 512

    // Keep 75% of each batch's rows with evict_last (best measured config),
    // stream the remaining 25% evict-first.
    const int resident_rows = (N * 3) / 4;  // 3072

    const int dyn_smem = DEPTH * STAGE_BYTES;   // 64 KB
    static bool attr_set = false;
    if (!attr_set) {
        cudaFuncSetAttribute(fused_kernel,
                             cudaFuncAttributeMaxDynamicSharedMemorySize, dyn_smem);
        attr_set = true;
    }

    dim3 grid(SLICES, B);                   // 16 x 64 = 1024 blocks
    fused_kernel<<<grid, 256, dyn_smem>>>(s_past, yq, y_past, w_mat, out, N, S,
                                          resident_rows);
}